// round 15
// baseline (speedup 1.0000x reference)
#include <cuda_runtime.h>
#include <cuda_bf16.h>
#include <math.h>
#include <stdint.h>

#define BATCH 4
#define SEQ   4096
#define DIM   128

// Scratch (allocation-free: __device__ globals)
__device__ __nv_bfloat16 g_inp_hi[(size_t)BATCH * SEQ * DIM];
__device__ __nv_bfloat16 g_inp_lo[(size_t)BATCH * SEQ * DIM];
__device__ __nv_bfloat16 g_key_hi[(size_t)BATCH * SEQ * DIM];
__device__ __nv_bfloat16 g_key_lo[(size_t)BATCH * SEQ * DIM];
__device__ __nv_bfloat16 g_val_hi[(size_t)BATCH * SEQ * DIM];
__device__ __nv_bfloat16 g_val_lo[(size_t)BATCH * SEQ * DIM];
__device__ __nv_bfloat16 g_ehi[(size_t)BATCH * SEQ * SEQ];   // E split hi
__device__ __nv_bfloat16 g_elo[(size_t)BATCH * SEQ * SEQ];   // E split lo
__device__ float g_part[(size_t)BATCH * SEQ * 64];
__device__ float g_sinv[(size_t)BATCH * SEQ];
__device__ float g_attn_fb[(size_t)BATCH * SEQ * SEQ];

// ---------------------------------------------------------------------------
// Helpers
// ---------------------------------------------------------------------------
__device__ __forceinline__ uint32_t smem_u32(const void* p) {
    return (uint32_t)__cvta_generic_to_shared(p);
}
__device__ __forceinline__ void cp16(uint32_t dst, const void* src) {
    asm volatile("cp.async.cg.shared.global [%0], [%1], 16;\n" :: "r"(dst), "l"(src));
}
__device__ __forceinline__ void cp_commit() {
    asm volatile("cp.async.commit_group;\n" ::);
}
__device__ __forceinline__ void cp_wait0() {
    asm volatile("cp.async.wait_group 0;\n" ::);
}
__device__ __forceinline__ void cp_wait1() {
    asm volatile("cp.async.wait_group 1;\n" ::);
}
__device__ __forceinline__ void ldsm4(uint32_t& r0, uint32_t& r1, uint32_t& r2, uint32_t& r3,
                                      uint32_t addr) {
    asm volatile("ldmatrix.sync.aligned.m8n8.x4.shared.b16 {%0,%1,%2,%3},[%4];\n"
                 : "=r"(r0), "=r"(r1), "=r"(r2), "=r"(r3) : "r"(addr));
}
__device__ __forceinline__ void ldsm4t(uint32_t& r0, uint32_t& r1, uint32_t& r2, uint32_t& r3,
                                       uint32_t addr) {
    asm volatile("ldmatrix.sync.aligned.m8n8.x4.trans.shared.b16 {%0,%1,%2,%3},[%4];\n"
                 : "=r"(r0), "=r"(r1), "=r"(r2), "=r"(r3) : "r"(addr));
}
__device__ __forceinline__ void mma16816(float* c, const uint32_t* a, uint32_t b0, uint32_t b1) {
    asm volatile(
        "mma.sync.aligned.m16n8k16.row.col.f32.bf16.bf16.f32 "
        "{%0,%1,%2,%3},{%4,%5,%6,%7},{%8,%9},{%0,%1,%2,%3};\n"
        : "+f"(c[0]), "+f"(c[1]), "+f"(c[2]), "+f"(c[3])
        : "r"(a[0]), "r"(a[1]), "r"(a[2]), "r"(a[3]), "r"(b0), "r"(b1));
}
__device__ __forceinline__ uint32_t bf2pack(float x, float y) {
    __nv_bfloat162 h = __floats2bfloat162_rn(x, y);
    return *reinterpret_cast<uint32_t*>(&h);
}
__device__ __forceinline__ void split_store(float4 f, __nv_bfloat16* hp, __nv_bfloat16* lp) {
    float h0 = __bfloat162float(__float2bfloat16(f.x));
    float h1 = __bfloat162float(__float2bfloat16(f.y));
    float h2 = __bfloat162float(__float2bfloat16(f.z));
    float h3 = __bfloat162float(__float2bfloat16(f.w));
    uint2 hi, lo;
    hi.x = bf2pack(f.x, f.y);
    hi.y = bf2pack(f.z, f.w);
    lo.x = bf2pack(f.x - h0, f.y - h1);
    lo.y = bf2pack(f.z - h2, f.w - h3);
    *reinterpret_cast<uint2*>(hp) = hi;
    *reinterpret_cast<uint2*>(lp) = lo;
}

// ---------------------------------------------------------------------------
// Prep: split inp fp32 -> hi/lo bf16
// ---------------------------------------------------------------------------
__global__ void __launch_bounds__(256) prep_inp_kernel(const float* __restrict__ inp) {
    size_t s = (size_t)blockIdx.x * 256 + threadIdx.x;
    float4 f = *reinterpret_cast<const float4*>(inp + s * 4);
    split_store(f, g_inp_hi + s * 4, g_inp_lo + s * 4);
}

// ---------------------------------------------------------------------------
// Projection: out[m,e] = sum_d inp[m,d] * w[e,d]; writes split bf16 K or V.
// ---------------------------------------------------------------------------
__global__ void __launch_bounds__(256) proj_kernel(const float* __restrict__ inp,
                                                   const float* __restrict__ w,
                                                   int which) {
    __nv_bfloat16* ohi = which ? g_val_hi : g_key_hi;
    __nv_bfloat16* olo = which ? g_val_lo : g_key_lo;
    __shared__ float As[16][128];
    __shared__ float Bs[16][128];

    const int tid   = threadIdx.x;
    const int mbase = blockIdx.x * 128;
    const int tm    = tid >> 4;
    const int tn    = tid & 15;

    float acc[8][8];
#pragma unroll
    for (int i = 0; i < 8; i++)
#pragma unroll
        for (int j = 0; j < 8; j++) acc[i][j] = 0.f;

    const int lr  = tid >> 2;
    const int lc4 = tid & 3;

    for (int k0 = 0; k0 < DIM; k0 += 16) {
#pragma unroll
        for (int it = 0; it < 2; ++it) {
            int row = lr + it * 64;
            float4 a = *reinterpret_cast<const float4*>(inp + (size_t)(mbase + row) * DIM + k0 + lc4 * 4);
            As[lc4 * 4 + 0][row] = a.x; As[lc4 * 4 + 1][row] = a.y;
            As[lc4 * 4 + 2][row] = a.z; As[lc4 * 4 + 3][row] = a.w;
            float4 bv = *reinterpret_cast<const float4*>(w + (size_t)row * DIM + k0 + lc4 * 4);
            Bs[lc4 * 4 + 0][row] = bv.x; Bs[lc4 * 4 + 1][row] = bv.y;
            Bs[lc4 * 4 + 2][row] = bv.z; Bs[lc4 * 4 + 3][row] = bv.w;
        }
        __syncthreads();
#pragma unroll
        for (int k = 0; k < 16; k++) {
            float am[8], bn[8];
#pragma unroll
            for (int i = 0; i < 8; i++) am[i] = As[k][tm * 8 + i];
#pragma unroll
            for (int j = 0; j < 8; j++) bn[j] = Bs[k][tn * 8 + j];
#pragma unroll
            for (int i = 0; i < 8; i++)
#pragma unroll
                for (int j = 0; j < 8; j++) acc[i][j] = fmaf(am[i], bn[j], acc[i][j]);
        }
        __syncthreads();
    }
#pragma unroll
    for (int i = 0; i < 8; i++) {
        size_t o = (size_t)(mbase + tm * 8 + i) * DIM + tn * 8;
        split_store(make_float4(acc[i][0], acc[i][1], acc[i][2], acc[i][3]), ohi + o, olo + o);
        split_store(make_float4(acc[i][4], acc[i][5], acc[i][6], acc[i][7]), ohi + o + 4, olo + o + 4);
    }
}

// ---------------------------------------------------------------------------
// Score+exp: E = mask ? 0 : exp(score); writes E as split bf16 (hi/lo) + row sums.
// CTA = 128(q) x 64(k). 8 warps, warp tile 32x32. cp.async staging, mask prefetch.
// ---------------------------------------------------------------------------
#define SA 136

__global__ void __launch_bounds__(256, 2) score_mma_kernel(const int* __restrict__ mask) {
    extern __shared__ char smraw[];
    __nv_bfloat16* Ahi = (__nv_bfloat16*)smraw;     // [128][SA]
    __nv_bfloat16* Alo = Ahi + 128 * SA;
    __nv_bfloat16* Bhi = Alo + 128 * SA;            // [64][SA]
    __nv_bfloat16* Blo = Bhi + 64 * SA;
    __shared__ float ssum[2][128];

    const int b  = blockIdx.z;
    const int qt = blockIdx.y;
    const int kt = blockIdx.x;
    const int tid = threadIdx.x;

    const __nv_bfloat16* sa_hi = g_inp_hi + ((size_t)b * SEQ + qt * 128) * DIM;
    const __nv_bfloat16* sa_lo = g_inp_lo + ((size_t)b * SEQ + qt * 128) * DIM;
    const __nv_bfloat16* sb_hi = g_key_hi + ((size_t)b * SEQ + kt * 64) * DIM;
    const __nv_bfloat16* sb_lo = g_key_lo + ((size_t)b * SEQ + kt * 64) * DIM;

    // Stage A/B hi/lo via cp.async
#pragma unroll
    for (int i = 0; i < 8; i++) {
        int s = tid + i * 256;
        int row = s >> 4, c8 = (s & 15) * 8;
        cp16(smem_u32(Ahi + row * SA + c8), sa_hi + (size_t)row * DIM + c8);
        cp16(smem_u32(Alo + row * SA + c8), sa_lo + (size_t)row * DIM + c8);
    }
#pragma unroll
    for (int i = 0; i < 4; i++) {
        int s = tid + i * 256;
        int row = s >> 4, c8 = (s & 15) * 8;
        cp16(smem_u32(Bhi + row * SA + c8), sb_hi + (size_t)row * DIM + c8);
        cp16(smem_u32(Blo + row * SA + c8), sb_lo + (size_t)row * DIM + c8);
    }
    cp_commit();

    const int lane = tid & 31, warp = tid >> 5;
    const int m0 = (warp >> 1) * 32;
    const int n0 = (warp & 1) * 32;
    const int r0 = lane >> 2, c0 = (lane & 3) * 2;

    // Prefetch mask into a 16-bit register bitmask (hidden behind MMA phase).
    uint32_t mbits = 0;
#pragma unroll
    for (int am = 0; am < 2; am++)
#pragma unroll
        for (int h = 0; h < 2; h++)
#pragma unroll
            for (int na = 0; na < 4; na++) {
                int gq = qt * 128 + m0 + am * 16 + r0 + h * 8;
                int gk = kt * 64 + n0 + na * 8 + c0;
                size_t idx = ((size_t)b * SEQ + gq) * SEQ + gk;
                int2 mv = *reinterpret_cast<const int2*>(mask + idx);
                int c = (am * 2 + h) * 4 + na;
                mbits |= (mv.x ? 1u : 0u) << (2 * c);
                mbits |= (mv.y ? 1u : 0u) << (2 * c + 1);
            }

    cp_wait0();
    __syncthreads();

    float acc[2][4][4];
#pragma unroll
    for (int i = 0; i < 2; i++)
#pragma unroll
        for (int j = 0; j < 4; j++)
#pragma unroll
            for (int r = 0; r < 4; r++) acc[i][j][r] = 0.f;

    const int a_row = lane & 15;
    const int a_col = (lane >> 4) << 3;
    const int b_row = (lane & 7) + ((lane >> 4) << 3);
    const int b_col = ((lane >> 3) & 1) << 3;

#pragma unroll
    for (int ks = 0; ks < 8; ks++) {
        const int k = ks * 16;
        uint32_t ah[2][4], al[2][4];
#pragma unroll
        for (int am = 0; am < 2; am++) {
            uint32_t ad = smem_u32(Ahi + (m0 + am * 16 + a_row) * SA + k + a_col);
            ldsm4(ah[am][0], ah[am][1], ah[am][2], ah[am][3], ad);
            ad = smem_u32(Alo + (m0 + am * 16 + a_row) * SA + k + a_col);
            ldsm4(al[am][0], al[am][1], al[am][2], al[am][3], ad);
        }
        uint32_t bh[2][4], bl[2][4];
#pragma unroll
        for (int bn = 0; bn < 2; bn++) {
            uint32_t ad = smem_u32(Bhi + (n0 + bn * 16 + b_row) * SA + k + b_col);
            ldsm4(bh[bn][0], bh[bn][1], bh[bn][2], bh[bn][3], ad);
            ad = smem_u32(Blo + (n0 + bn * 16 + b_row) * SA + k + b_col);
            ldsm4(bl[bn][0], bl[bn][1], bl[bn][2], bl[bn][3], ad);
        }
#pragma unroll
        for (int am = 0; am < 2; am++)
#pragma unroll
            for (int na = 0; na < 4; na++) {
                const int g = na >> 1, o = (na & 1) * 2;
                mma16816(acc[am][na], ah[am], bh[g][o], bh[g][o + 1]);
                mma16816(acc[am][na], ah[am], bl[g][o], bl[g][o + 1]);
                mma16816(acc[am][na], al[am], bh[g][o], bh[g][o + 1]);
            }
    }

    // Epilogue: E = mask ? 0 : __expf(score*scale); write split bf16; row sums.
    const float scale = 0.08838834764831845f;
#pragma unroll
    for (int am = 0; am < 2; am++)
#pragma unroll
        for (int h = 0; h < 2; h++) {
            float rs = 0.f;
#pragma unroll
            for (int na = 0; na < 4; na++) {
                int gq = qt * 128 + m0 + am * 16 + r0 + h * 8;
                int gk = kt * 64 + n0 + na * 8 + c0;
                size_t idx = ((size_t)b * SEQ + gq) * SEQ + gk;
                int c = (am * 2 + h) * 4 + na;
                float ox = ((mbits >> (2 * c)) & 1u) ? 0.f : __expf(acc[am][na][h * 2 + 0] * scale);
                float oy = ((mbits >> (2 * c + 1)) & 1u) ? 0.f : __expf(acc[am][na][h * 2 + 1] * scale);
                rs += ox + oy;
                float hx = __bfloat162float(__float2bfloat16(ox));
                float hy = __bfloat162float(__float2bfloat16(oy));
                *reinterpret_cast<uint32_t*>(g_ehi + idx) = bf2pack(ox, oy);
                *reinterpret_cast<uint32_t*>(g_elo + idx) = bf2pack(ox - hx, oy - hy);
            }
            rs += __shfl_xor_sync(0xffffffffu, rs, 1);
            rs += __shfl_xor_sync(0xffffffffu, rs, 2);
            if ((lane & 3) == 0)
                ssum[warp & 1][m0 + am * 16 + r0 + h * 8] = rs;
        }
    __syncthreads();
    if (tid < 128) {
        g_part[((size_t)b * SEQ + qt * 128 + tid) * 64 + kt] = ssum[0][tid] + ssum[1][tid];
    }
}

// ---------------------------------------------------------------------------
// Row-sum reduce: s_inv[row] = 1 / sum_j part[row][j]
// ---------------------------------------------------------------------------
__global__ void __launch_bounds__(256) sums_kernel() {
    int row = blockIdx.x * 256 + threadIdx.x;
    const float* pp = g_part + (size_t)row * 64;
    float s = 0.f;
#pragma unroll
    for (int j = 0; j < 64; j += 4) {
        float4 v = *reinterpret_cast<const float4*>(pp + j);
        s += v.x + v.y + v.z + v.w;
    }
    g_sinv[row] = 1.f / s;
}

// ---------------------------------------------------------------------------
// Fused normalize + PV (normalization commutes with matmul):
//   out = diag(inv) * (E @ V);  attn = E * inv  (written from smem tile).
// CTA = 64(q) x 128(d); k-chunks of 64, cp.async double-buffered.
// 8 warps, warp tile 32x32. smem 2 stages x 53KB -> 2 CTAs/SM.
// ---------------------------------------------------------------------------
#define SE 72
#define SV 136
#define STAGE_ELEMS (2 * 64 * SE + 2 * 64 * SV)   // 26624 bf16 elems

__global__ void __launch_bounds__(256, 2) normpv_kernel(float* __restrict__ attn,
                                                        float* __restrict__ out) {
    extern __shared__ char smraw[];
    __nv_bfloat16* base = (__nv_bfloat16*)smraw;
    __shared__ float s_inv[64];

    const int b  = blockIdx.y;
    const int qb = blockIdx.x * 64;
    const int tid = threadIdx.x;

    const size_t ebase = ((size_t)b * SEQ + qb) * SEQ;
    const size_t vbase = (size_t)b * SEQ * DIM;

    if (tid < 64) s_inv[tid] = g_sinv[(size_t)b * SEQ + qb + tid];

    const int lane = tid & 31, warp = tid >> 5;
    const int m0 = (warp >> 2) * 32;   // q (2 groups)
    const int n0 = (warp & 3) * 32;    // d (4 groups)

    float acc[2][4][4];
#pragma unroll
    for (int i = 0; i < 2; i++)
#pragma unroll
        for (int j = 0; j < 4; j++)
#pragma unroll
            for (int r = 0; r < 4; r++) acc[i][j][r] = 0.f;

    const int a_row = lane & 15;
    const int a_col = (lane >> 4) << 3;
    const int v_row = (lane & 7) + (((lane >> 3) & 1) << 3);
    const int v_col = (lane >> 4) << 3;

    // Per-thread staging coordinates
    const int e_row = tid >> 3, e_c8 = (tid & 7) * 8;       // + i*32 rows? no: 2 iters cover 512 slots
    const int v_row_st = tid >> 4, v_c8 = (tid & 15) * 8;

    // issue one stage of cp.async loads
    auto issue_stage = [&](int kc, int buf) {
        __nv_bfloat16* Eh = base + (size_t)buf * STAGE_ELEMS;
        __nv_bfloat16* El = Eh + 64 * SE;
        __nv_bfloat16* Vh = El + 64 * SE;
        __nv_bfloat16* Vl = Vh + 64 * SV;
        const int kb = kc * 64;
#pragma unroll
        for (int i = 0; i < 2; i++) {
            int s = tid + i * 256;
            int row = s >> 3, c8 = (s & 7) * 8;
            cp16(smem_u32(Eh + row * SE + c8), g_ehi + ebase + (size_t)row * SEQ + kb + c8);
            cp16(smem_u32(El + row * SE + c8), g_elo + ebase + (size_t)row * SEQ + kb + c8);
        }
#pragma unroll
        for (int i = 0; i < 4; i++) {
            int s = tid + i * 256;
            int row = s >> 4, c8 = (s & 15) * 8;
            cp16(smem_u32(Vh + row * SV + c8), g_val_hi + vbase + (size_t)(kb + row) * DIM + c8);
            cp16(smem_u32(Vl + row * SV + c8), g_val_lo + vbase + (size_t)(kb + row) * DIM + c8);
        }
        cp_commit();
    };

    issue_stage(0, 0);

    for (int kc = 0; kc < SEQ / 64; kc++) {
        const int buf = kc & 1;
        if (kc + 1 < SEQ / 64) {
            issue_stage(kc + 1, (kc + 1) & 1);
            cp_wait1();
        } else {
            cp_wait0();
        }
        __syncthreads();

        __nv_bfloat16* Eh = base + (size_t)buf * STAGE_ELEMS;
        __nv_bfloat16* El = Eh + 64 * SE;
        __nv_bfloat16* Vh = El + 64 * SE;
        __nv_bfloat16* Vl = Vh + 64 * SV;
        const int kb = kc * 64;

        // attn = (hi+lo) * inv, written straight from the smem tile
#pragma unroll
        for (int i = 0; i < 2; i++) {
            int s = tid + i * 256;
            int row = s >> 3, c8 = (s & 7) * 8;
            uint4 h4 = *reinterpret_cast<const uint4*>(Eh + row * SE + c8);
            uint4 l4 = *reinterpret_cast<const uint4*>(El + row * SE + c8);
            float inv = s_inv[row];
            float4 o0, o1;
            {
                float2 h0 = __bfloat1622float2(*reinterpret_cast<__nv_bfloat162*>(&h4.x));
                float2 l0 = __bfloat1622float2(*reinterpret_cast<__nv_bfloat162*>(&l4.x));
                float2 h1 = __bfloat1622float2(*reinterpret_cast<__nv_bfloat162*>(&h4.y));
                float2 l1 = __bfloat1622float2(*reinterpret_cast<__nv_bfloat162*>(&l4.y));
                o0 = make_float4((h0.x + l0.x) * inv, (h0.y + l0.y) * inv,
                                 (h1.x + l1.x) * inv, (h1.y + l1.y) * inv);
                float2 h2 = __bfloat1622float2(*reinterpret_cast<__nv_bfloat162*>(&h4.z));
                float2 l2 = __bfloat1622float2(*reinterpret_cast<__nv_bfloat162*>(&l4.z));
                float2 h3 = __bfloat1622float2(*reinterpret_cast<__nv_bfloat162*>(&h4.w));
                float2 l3 = __bfloat1622float2(*reinterpret_cast<__nv_bfloat162*>(&l4.w));
                o1 = make_float4((h2.x + l2.x) * inv, (h2.y + l2.y) * inv,
                                 (h3.x + l3.x) * inv, (h3.y + l3.y) * inv);
            }
            float* ap = attn + ebase + (size_t)row * SEQ + kb + c8;
            *reinterpret_cast<float4*>(ap)     = o0;
            *reinterpret_cast<float4*>(ap + 4) = o1;
        }

        // MMA: acc += E_tile @ V_tile (split 3-pass)
#pragma unroll
        for (int ks = 0; ks < 4; ks++) {
            const int k = ks * 16;
            uint32_t ah[2][4], al[2][4];
#pragma unroll
            for (int am = 0; am < 2; am++) {
                uint32_t ad = smem_u32(Eh + (m0 + am * 16 + a_row) * SE + k + a_col);
                ldsm4(ah[am][0], ah[am][1], ah[am][2], ah[am][3], ad);
                ad = smem_u32(El + (m0 + am * 16 + a_row) * SE + k + a_col);
                ldsm4(al[am][0], al[am][1], al[am][2], al[am][3], ad);
            }
            uint32_t bh[2][4], bl[2][4];
#pragma unroll
            for (int bn = 0; bn < 2; bn++) {
                uint32_t ad = smem_u32(Vh + (k + v_row) * SV + n0 + bn * 16 + v_col);
                ldsm4t(bh[bn][0], bh[bn][1], bh[bn][2], bh[bn][3], ad);
                ad = smem_u32(Vl + (k + v_row) * SV + n0 + bn * 16 + v_col);
                ldsm4t(bl[bn][0], bl[bn][1], bl[bn][2], bl[bn][3], ad);
            }
#pragma unroll
            for (int am = 0; am < 2; am++)
#pragma unroll
                for (int na = 0; na < 4; na++) {
                    const int g = na >> 1, o = (na & 1) * 2;
                    mma16816(acc[am][na], ah[am], bh[g][o], bh[g][o + 1]);
                    mma16816(acc[am][na], ah[am], bl[g][o], bl[g][o + 1]);
                    mma16816(acc[am][na], al[am], bh[g][o], bh[g][o + 1]);
                }
        }
        __syncthreads();
    }

    // Epilogue: out = acc * inv[row]
    const int r0 = lane >> 2, c0 = (lane & 3) * 2;
#pragma unroll
    for (int am = 0; am < 2; am++) {
#pragma unroll
        for (int h = 0; h < 2; h++) {
            int lq = m0 + am * 16 + r0 + h * 8;
            float inv = s_inv[lq];
#pragma unroll
            for (int na = 0; na < 4; na++) {
                int gd = n0 + na * 8 + c0;
                size_t idx = ((size_t)b * SEQ + qb + lq) * DIM + gd;
                float2 o;
                o.x = acc[am][na][h * 2 + 0] * inv;
                o.y = acc[am][na][h * 2 + 1] * inv;
                *reinterpret_cast<float2*>(out + idx) = o;
            }
        }
    }
}

// ---------------------------------------------------------------------------
extern "C" void kernel_launch(void* const* d_in, const int* in_sizes, int n_in,
                              void* d_out, int out_size) {
    const float* inp  = (const float*)d_in[0];
    const float* w_k  = (const float*)d_in[1];
    const float* w_v  = (const float*)d_in[2];
    const int*   mask = (const int*)d_in[3];
    float* outp = (float*)d_out;

    const size_t BSD = (size_t)BATCH * SEQ * DIM;
    const size_t BSS = (size_t)BATCH * SEQ * SEQ;

    float* attn;
    if ((size_t)out_size >= BSD + BSS) {
        attn = outp + BSD;
    } else {
        void* p = nullptr;
        cudaGetSymbolAddress(&p, g_attn_fb);
        attn = (float*)p;
    }

    const int score_smem = 384 * SA * 2;                    // 104448
    const int pv_smem    = 2 * STAGE_ELEMS * 2;             // 106496
    cudaFuncSetAttribute(score_mma_kernel, cudaFuncAttributeMaxDynamicSharedMemorySize, score_smem);
    cudaFuncSetAttribute(normpv_kernel, cudaFuncAttributeMaxDynamicSharedMemorySize, pv_smem);

    prep_inp_kernel<<<(BATCH * SEQ * DIM) / (256 * 4), 256>>>(inp);
    proj_kernel<<<(BATCH * SEQ) / 128, 256>>>(inp, w_k, 0);
    proj_kernel<<<(BATCH * SEQ) / 128, 256>>>(inp, w_v, 1);
    score_mma_kernel<<<dim3(SEQ / 64, SEQ / 128, BATCH), 256, score_smem>>>(mask);
    sums_kernel<<<(BATCH * SEQ) / 256, 256>>>();
    normpv_kernel<<<dim3(SEQ / 64, BATCH), 256, pv_smem>>>(attn, outp);
}

// round 16
// speedup vs baseline: 1.0019x; 1.0019x over previous
#include <cuda_runtime.h>
#include <cuda_bf16.h>
#include <math.h>
#include <stdint.h>

#define BATCH 4
#define SEQ   4096
#define DIM   128

// Scratch (allocation-free: __device__ globals)
__device__ __nv_bfloat16 g_inp_hi[(size_t)BATCH * SEQ * DIM];
__device__ __nv_bfloat16 g_inp_lo[(size_t)BATCH * SEQ * DIM];
__device__ __nv_bfloat16 g_key_hi[(size_t)BATCH * SEQ * DIM];
__device__ __nv_bfloat16 g_key_lo[(size_t)BATCH * SEQ * DIM];
__device__ __nv_bfloat16 g_val_hi[(size_t)BATCH * SEQ * DIM];
__device__ __nv_bfloat16 g_val_lo[(size_t)BATCH * SEQ * DIM];
__device__ __nv_bfloat16 g_ehi[(size_t)BATCH * SEQ * SEQ];   // E split hi
__device__ __nv_bfloat16 g_elo[(size_t)BATCH * SEQ * SEQ];   // E split lo
__device__ float g_part[(size_t)BATCH * SEQ * 64];
__device__ float g_sinv[(size_t)BATCH * SEQ];
__device__ float g_attn_fb[(size_t)BATCH * SEQ * SEQ];

// ---------------------------------------------------------------------------
// Helpers
// ---------------------------------------------------------------------------
__device__ __forceinline__ uint32_t smem_u32(const void* p) {
    return (uint32_t)__cvta_generic_to_shared(p);
}
__device__ __forceinline__ void cp16(uint32_t dst, const void* src) {
    asm volatile("cp.async.cg.shared.global [%0], [%1], 16;\n" :: "r"(dst), "l"(src));
}
__device__ __forceinline__ void cp_commit() {
    asm volatile("cp.async.commit_group;\n" ::);
}
__device__ __forceinline__ void cp_wait0() {
    asm volatile("cp.async.wait_group 0;\n" ::);
}
__device__ __forceinline__ void cp_wait1() {
    asm volatile("cp.async.wait_group 1;\n" ::);
}
__device__ __forceinline__ void ldsm4(uint32_t& r0, uint32_t& r1, uint32_t& r2, uint32_t& r3,
                                      uint32_t addr) {
    asm volatile("ldmatrix.sync.aligned.m8n8.x4.shared.b16 {%0,%1,%2,%3},[%4];\n"
                 : "=r"(r0), "=r"(r1), "=r"(r2), "=r"(r3) : "r"(addr));
}
__device__ __forceinline__ void ldsm4t(uint32_t& r0, uint32_t& r1, uint32_t& r2, uint32_t& r3,
                                       uint32_t addr) {
    asm volatile("ldmatrix.sync.aligned.m8n8.x4.trans.shared.b16 {%0,%1,%2,%3},[%4];\n"
                 : "=r"(r0), "=r"(r1), "=r"(r2), "=r"(r3) : "r"(addr));
}
__device__ __forceinline__ void mma16816(float* c, const uint32_t* a, uint32_t b0, uint32_t b1) {
    asm volatile(
        "mma.sync.aligned.m16n8k16.row.col.f32.bf16.bf16.f32 "
        "{%0,%1,%2,%3},{%4,%5,%6,%7},{%8,%9},{%0,%1,%2,%3};\n"
        : "+f"(c[0]), "+f"(c[1]), "+f"(c[2]), "+f"(c[3])
        : "r"(a[0]), "r"(a[1]), "r"(a[2]), "r"(a[3]), "r"(b0), "r"(b1));
}
__device__ __forceinline__ uint32_t bf2pack(float x, float y) {
    __nv_bfloat162 h = __floats2bfloat162_rn(x, y);
    return *reinterpret_cast<uint32_t*>(&h);
}
__device__ __forceinline__ void split_store(float4 f, __nv_bfloat16* hp, __nv_bfloat16* lp) {
    float h0 = __bfloat162float(__float2bfloat16(f.x));
    float h1 = __bfloat162float(__float2bfloat16(f.y));
    float h2 = __bfloat162float(__float2bfloat16(f.z));
    float h3 = __bfloat162float(__float2bfloat16(f.w));
    uint2 hi, lo;
    hi.x = bf2pack(f.x, f.y);
    hi.y = bf2pack(f.z, f.w);
    lo.x = bf2pack(f.x - h0, f.y - h1);
    lo.y = bf2pack(f.z - h2, f.w - h3);
    *reinterpret_cast<uint2*>(hp) = hi;
    *reinterpret_cast<uint2*>(lp) = lo;
}

// ---------------------------------------------------------------------------
// Prep: split inp fp32 -> hi/lo bf16
// ---------------------------------------------------------------------------
__global__ void __launch_bounds__(256) prep_inp_kernel(const float* __restrict__ inp) {
    size_t s = (size_t)blockIdx.x * 256 + threadIdx.x;
    float4 f = *reinterpret_cast<const float4*>(inp + s * 4);
    split_store(f, g_inp_hi + s * 4, g_inp_lo + s * 4);
}

// ---------------------------------------------------------------------------
// Projection: out[m,e] = sum_d inp[m,d] * w[e,d]; writes split bf16 K or V.
// ---------------------------------------------------------------------------
__global__ void __launch_bounds__(256) proj_kernel(const float* __restrict__ inp,
                                                   const float* __restrict__ w,
                                                   int which) {
    __nv_bfloat16* ohi = which ? g_val_hi : g_key_hi;
    __nv_bfloat16* olo = which ? g_val_lo : g_key_lo;
    __shared__ float As[16][128];
    __shared__ float Bs[16][128];

    const int tid   = threadIdx.x;
    const int mbase = blockIdx.x * 128;
    const int tm    = tid >> 4;
    const int tn    = tid & 15;

    float acc[8][8];
#pragma unroll
    for (int i = 0; i < 8; i++)
#pragma unroll
        for (int j = 0; j < 8; j++) acc[i][j] = 0.f;

    const int lr  = tid >> 2;
    const int lc4 = tid & 3;

    for (int k0 = 0; k0 < DIM; k0 += 16) {
#pragma unroll
        for (int it = 0; it < 2; ++it) {
            int row = lr + it * 64;
            float4 a = *reinterpret_cast<const float4*>(inp + (size_t)(mbase + row) * DIM + k0 + lc4 * 4);
            As[lc4 * 4 + 0][row] = a.x; As[lc4 * 4 + 1][row] = a.y;
            As[lc4 * 4 + 2][row] = a.z; As[lc4 * 4 + 3][row] = a.w;
            float4 bv = *reinterpret_cast<const float4*>(w + (size_t)row * DIM + k0 + lc4 * 4);
            Bs[lc4 * 4 + 0][row] = bv.x; Bs[lc4 * 4 + 1][row] = bv.y;
            Bs[lc4 * 4 + 2][row] = bv.z; Bs[lc4 * 4 + 3][row] = bv.w;
        }
        __syncthreads();
#pragma unroll
        for (int k = 0; k < 16; k++) {
            float am[8], bn[8];
#pragma unroll
            for (int i = 0; i < 8; i++) am[i] = As[k][tm * 8 + i];
#pragma unroll
            for (int j = 0; j < 8; j++) bn[j] = Bs[k][tn * 8 + j];
#pragma unroll
            for (int i = 0; i < 8; i++)
#pragma unroll
                for (int j = 0; j < 8; j++) acc[i][j] = fmaf(am[i], bn[j], acc[i][j]);
        }
        __syncthreads();
    }
#pragma unroll
    for (int i = 0; i < 8; i++) {
        size_t o = (size_t)(mbase + tm * 8 + i) * DIM + tn * 8;
        split_store(make_float4(acc[i][0], acc[i][1], acc[i][2], acc[i][3]), ohi + o, olo + o);
        split_store(make_float4(acc[i][4], acc[i][5], acc[i][6], acc[i][7]), ohi + o + 4, olo + o + 4);
    }
}

// ---------------------------------------------------------------------------
// Score+exp: E = mask ? 0 : exp(score); writes E as split bf16 (hi/lo) + row sums.
// CTA = 128(q) x 64(k). 8 warps, warp tile 32x32. cp.async staging, mask prefetch.
// ---------------------------------------------------------------------------
#define SA 136

__global__ void __launch_bounds__(256, 2) score_mma_kernel(const int* __restrict__ mask) {
    extern __shared__ char smraw[];
    __nv_bfloat16* Ahi = (__nv_bfloat16*)smraw;     // [128][SA]
    __nv_bfloat16* Alo = Ahi + 128 * SA;
    __nv_bfloat16* Bhi = Alo + 128 * SA;            // [64][SA]
    __nv_bfloat16* Blo = Bhi + 64 * SA;
    __shared__ float ssum[2][128];

    const int b  = blockIdx.z;
    const int qt = blockIdx.y;
    const int kt = blockIdx.x;
    const int tid = threadIdx.x;

    const __nv_bfloat16* sa_hi = g_inp_hi + ((size_t)b * SEQ + qt * 128) * DIM;
    const __nv_bfloat16* sa_lo = g_inp_lo + ((size_t)b * SEQ + qt * 128) * DIM;
    const __nv_bfloat16* sb_hi = g_key_hi + ((size_t)b * SEQ + kt * 64) * DIM;
    const __nv_bfloat16* sb_lo = g_key_lo + ((size_t)b * SEQ + kt * 64) * DIM;

    // Stage A/B hi/lo via cp.async
#pragma unroll
    for (int i = 0; i < 8; i++) {
        int s = tid + i * 256;
        int row = s >> 4, c8 = (s & 15) * 8;
        cp16(smem_u32(Ahi + row * SA + c8), sa_hi + (size_t)row * DIM + c8);
        cp16(smem_u32(Alo + row * SA + c8), sa_lo + (size_t)row * DIM + c8);
    }
#pragma unroll
    for (int i = 0; i < 4; i++) {
        int s = tid + i * 256;
        int row = s >> 4, c8 = (s & 15) * 8;
        cp16(smem_u32(Bhi + row * SA + c8), sb_hi + (size_t)row * DIM + c8);
        cp16(smem_u32(Blo + row * SA + c8), sb_lo + (size_t)row * DIM + c8);
    }
    cp_commit();

    const int lane = tid & 31, warp = tid >> 5;
    const int m0 = (warp >> 1) * 32;
    const int n0 = (warp & 1) * 32;
    const int r0 = lane >> 2, c0 = (lane & 3) * 2;

    // Prefetch mask into a 16-bit register bitmask (hidden behind MMA phase).
    uint32_t mbits = 0;
#pragma unroll
    for (int am = 0; am < 2; am++)
#pragma unroll
        for (int h = 0; h < 2; h++)
#pragma unroll
            for (int na = 0; na < 4; na++) {
                int gq = qt * 128 + m0 + am * 16 + r0 + h * 8;
                int gk = kt * 64 + n0 + na * 8 + c0;
                size_t idx = ((size_t)b * SEQ + gq) * SEQ + gk;
                int2 mv = *reinterpret_cast<const int2*>(mask + idx);
                int c = (am * 2 + h) * 4 + na;
                mbits |= (mv.x ? 1u : 0u) << (2 * c);
                mbits |= (mv.y ? 1u : 0u) << (2 * c + 1);
            }

    cp_wait0();
    __syncthreads();

    float acc[2][4][4];
#pragma unroll
    for (int i = 0; i < 2; i++)
#pragma unroll
        for (int j = 0; j < 4; j++)
#pragma unroll
            for (int r = 0; r < 4; r++) acc[i][j][r] = 0.f;

    const int a_row = lane & 15;
    const int a_col = (lane >> 4) << 3;
    const int b_row = (lane & 7) + ((lane >> 4) << 3);
    const int b_col = ((lane >> 3) & 1) << 3;

#pragma unroll
    for (int ks = 0; ks < 8; ks++) {
        const int k = ks * 16;
        uint32_t ah[2][4], al[2][4];
#pragma unroll
        for (int am = 0; am < 2; am++) {
            uint32_t ad = smem_u32(Ahi + (m0 + am * 16 + a_row) * SA + k + a_col);
            ldsm4(ah[am][0], ah[am][1], ah[am][2], ah[am][3], ad);
            ad = smem_u32(Alo + (m0 + am * 16 + a_row) * SA + k + a_col);
            ldsm4(al[am][0], al[am][1], al[am][2], al[am][3], ad);
        }
        uint32_t bh[2][4], bl[2][4];
#pragma unroll
        for (int bn = 0; bn < 2; bn++) {
            uint32_t ad = smem_u32(Bhi + (n0 + bn * 16 + b_row) * SA + k + b_col);
            ldsm4(bh[bn][0], bh[bn][1], bh[bn][2], bh[bn][3], ad);
            ad = smem_u32(Blo + (n0 + bn * 16 + b_row) * SA + k + b_col);
            ldsm4(bl[bn][0], bl[bn][1], bl[bn][2], bl[bn][3], ad);
        }
#pragma unroll
        for (int am = 0; am < 2; am++)
#pragma unroll
            for (int na = 0; na < 4; na++) {
                const int g = na >> 1, o = (na & 1) * 2;
                mma16816(acc[am][na], ah[am], bh[g][o], bh[g][o + 1]);
                mma16816(acc[am][na], ah[am], bl[g][o], bl[g][o + 1]);
                mma16816(acc[am][na], al[am], bh[g][o], bh[g][o + 1]);
            }
    }

    // Epilogue: E = mask ? 0 : __expf(score*scale); write split bf16; row sums.
    const float scale = 0.08838834764831845f;
#pragma unroll
    for (int am = 0; am < 2; am++)
#pragma unroll
        for (int h = 0; h < 2; h++) {
            float rs = 0.f;
#pragma unroll
            for (int na = 0; na < 4; na++) {
                int gq = qt * 128 + m0 + am * 16 + r0 + h * 8;
                int gk = kt * 64 + n0 + na * 8 + c0;
                size_t idx = ((size_t)b * SEQ + gq) * SEQ + gk;
                int c = (am * 2 + h) * 4 + na;
                float ox = ((mbits >> (2 * c)) & 1u) ? 0.f : __expf(acc[am][na][h * 2 + 0] * scale);
                float oy = ((mbits >> (2 * c + 1)) & 1u) ? 0.f : __expf(acc[am][na][h * 2 + 1] * scale);
                rs += ox + oy;
                float hx = __bfloat162float(__float2bfloat16(ox));
                float hy = __bfloat162float(__float2bfloat16(oy));
                *reinterpret_cast<uint32_t*>(g_ehi + idx) = bf2pack(ox, oy);
                *reinterpret_cast<uint32_t*>(g_elo + idx) = bf2pack(ox - hx, oy - hy);
            }
            rs += __shfl_xor_sync(0xffffffffu, rs, 1);
            rs += __shfl_xor_sync(0xffffffffu, rs, 2);
            if ((lane & 3) == 0)
                ssum[warp & 1][m0 + am * 16 + r0 + h * 8] = rs;
        }
    __syncthreads();
    if (tid < 128) {
        g_part[((size_t)b * SEQ + qt * 128 + tid) * 64 + kt] = ssum[0][tid] + ssum[1][tid];
    }
}

// ---------------------------------------------------------------------------
// Row-sum reduce: s_inv[row] = 1 / sum_j part[row][j]
// ---------------------------------------------------------------------------
__global__ void __launch_bounds__(256) sums_kernel() {
    int row = blockIdx.x * 256 + threadIdx.x;
    const float* pp = g_part + (size_t)row * 64;
    float s = 0.f;
#pragma unroll
    for (int j = 0; j < 64; j += 4) {
        float4 v = *reinterpret_cast<const float4*>(pp + j);
        s += v.x + v.y + v.z + v.w;
    }
    g_sinv[row] = 1.f / s;
}

// ---------------------------------------------------------------------------
// Fused normalize + PV (normalization commutes with matmul):
//   out = diag(inv) * (E @ V);  attn = E * inv  (written from smem tile).
// CTA = 64(q) x 128(d); k-chunks of 64, cp.async double-buffered.
// 8 warps, warp tile 32x32. smem 2 stages x 53KB -> 2 CTAs/SM.
// ---------------------------------------------------------------------------
#define SE 72
#define SV 136
#define STAGE_ELEMS (2 * 64 * SE + 2 * 64 * SV)   // 26624 bf16 elems

__global__ void __launch_bounds__(256, 2) normpv_kernel(float* __restrict__ attn,
                                                        float* __restrict__ out) {
    extern __shared__ char smraw[];
    __nv_bfloat16* base = (__nv_bfloat16*)smraw;
    __shared__ float s_inv[64];

    const int b  = blockIdx.y;
    const int qb = blockIdx.x * 64;
    const int tid = threadIdx.x;

    const size_t ebase = ((size_t)b * SEQ + qb) * SEQ;
    const size_t vbase = (size_t)b * SEQ * DIM;

    if (tid < 64) s_inv[tid] = g_sinv[(size_t)b * SEQ + qb + tid];

    const int lane = tid & 31, warp = tid >> 5;
    const int m0 = (warp >> 2) * 32;   // q (2 groups)
    const int n0 = (warp & 3) * 32;    // d (4 groups)

    float acc[2][4][4];
#pragma unroll
    for (int i = 0; i < 2; i++)
#pragma unroll
        for (int j = 0; j < 4; j++)
#pragma unroll
            for (int r = 0; r < 4; r++) acc[i][j][r] = 0.f;

    const int a_row = lane & 15;
    const int a_col = (lane >> 4) << 3;
    const int v_row = (lane & 7) + (((lane >> 3) & 1) << 3);
    const int v_col = (lane >> 4) << 3;

    // Per-thread staging coordinates
    const int e_row = tid >> 3, e_c8 = (tid & 7) * 8;       // + i*32 rows? no: 2 iters cover 512 slots
    const int v_row_st = tid >> 4, v_c8 = (tid & 15) * 8;

    // issue one stage of cp.async loads
    auto issue_stage = [&](int kc, int buf) {
        __nv_bfloat16* Eh = base + (size_t)buf * STAGE_ELEMS;
        __nv_bfloat16* El = Eh + 64 * SE;
        __nv_bfloat16* Vh = El + 64 * SE;
        __nv_bfloat16* Vl = Vh + 64 * SV;
        const int kb = kc * 64;
#pragma unroll
        for (int i = 0; i < 2; i++) {
            int s = tid + i * 256;
            int row = s >> 3, c8 = (s & 7) * 8;
            cp16(smem_u32(Eh + row * SE + c8), g_ehi + ebase + (size_t)row * SEQ + kb + c8);
            cp16(smem_u32(El + row * SE + c8), g_elo + ebase + (size_t)row * SEQ + kb + c8);
        }
#pragma unroll
        for (int i = 0; i < 4; i++) {
            int s = tid + i * 256;
            int row = s >> 4, c8 = (s & 15) * 8;
            cp16(smem_u32(Vh + row * SV + c8), g_val_hi + vbase + (size_t)(kb + row) * DIM + c8);
            cp16(smem_u32(Vl + row * SV + c8), g_val_lo + vbase + (size_t)(kb + row) * DIM + c8);
        }
        cp_commit();
    };

    issue_stage(0, 0);

    for (int kc = 0; kc < SEQ / 64; kc++) {
        const int buf = kc & 1;
        if (kc + 1 < SEQ / 64) {
            issue_stage(kc + 1, (kc + 1) & 1);
            cp_wait1();
        } else {
            cp_wait0();
        }
        __syncthreads();

        __nv_bfloat16* Eh = base + (size_t)buf * STAGE_ELEMS;
        __nv_bfloat16* El = Eh + 64 * SE;
        __nv_bfloat16* Vh = El + 64 * SE;
        __nv_bfloat16* Vl = Vh + 64 * SV;
        const int kb = kc * 64;

        // attn = (hi+lo) * inv, written straight from the smem tile
#pragma unroll
        for (int i = 0; i < 2; i++) {
            int s = tid + i * 256;
            int row = s >> 3, c8 = (s & 7) * 8;
            uint4 h4 = *reinterpret_cast<const uint4*>(Eh + row * SE + c8);
            uint4 l4 = *reinterpret_cast<const uint4*>(El + row * SE + c8);
            float inv = s_inv[row];
            float4 o0, o1;
            {
                float2 h0 = __bfloat1622float2(*reinterpret_cast<__nv_bfloat162*>(&h4.x));
                float2 l0 = __bfloat1622float2(*reinterpret_cast<__nv_bfloat162*>(&l4.x));
                float2 h1 = __bfloat1622float2(*reinterpret_cast<__nv_bfloat162*>(&h4.y));
                float2 l1 = __bfloat1622float2(*reinterpret_cast<__nv_bfloat162*>(&l4.y));
                o0 = make_float4((h0.x + l0.x) * inv, (h0.y + l0.y) * inv,
                                 (h1.x + l1.x) * inv, (h1.y + l1.y) * inv);
                float2 h2 = __bfloat1622float2(*reinterpret_cast<__nv_bfloat162*>(&h4.z));
                float2 l2 = __bfloat1622float2(*reinterpret_cast<__nv_bfloat162*>(&l4.z));
                float2 h3 = __bfloat1622float2(*reinterpret_cast<__nv_bfloat162*>(&h4.w));
                float2 l3 = __bfloat1622float2(*reinterpret_cast<__nv_bfloat162*>(&l4.w));
                o1 = make_float4((h2.x + l2.x) * inv, (h2.y + l2.y) * inv,
                                 (h3.x + l3.x) * inv, (h3.y + l3.y) * inv);
            }
            float* ap = attn + ebase + (size_t)row * SEQ + kb + c8;
            *reinterpret_cast<float4*>(ap)     = o0;
            *reinterpret_cast<float4*>(ap + 4) = o1;
        }

        // MMA: acc += E_tile @ V_tile (split 3-pass)
#pragma unroll
        for (int ks = 0; ks < 4; ks++) {
            const int k = ks * 16;
            uint32_t ah[2][4], al[2][4];
#pragma unroll
            for (int am = 0; am < 2; am++) {
                uint32_t ad = smem_u32(Eh + (m0 + am * 16 + a_row) * SE + k + a_col);
                ldsm4(ah[am][0], ah[am][1], ah[am][2], ah[am][3], ad);
                ad = smem_u32(El + (m0 + am * 16 + a_row) * SE + k + a_col);
                ldsm4(al[am][0], al[am][1], al[am][2], al[am][3], ad);
            }
            uint32_t bh[2][4], bl[2][4];
#pragma unroll
            for (int bn = 0; bn < 2; bn++) {
                uint32_t ad = smem_u32(Vh + (k + v_row) * SV + n0 + bn * 16 + v_col);
                ldsm4t(bh[bn][0], bh[bn][1], bh[bn][2], bh[bn][3], ad);
                ad = smem_u32(Vl + (k + v_row) * SV + n0 + bn * 16 + v_col);
                ldsm4t(bl[bn][0], bl[bn][1], bl[bn][2], bl[bn][3], ad);
            }
#pragma unroll
            for (int am = 0; am < 2; am++)
#pragma unroll
                for (int na = 0; na < 4; na++) {
                    const int g = na >> 1, o = (na & 1) * 2;
                    mma16816(acc[am][na], ah[am], bh[g][o], bh[g][o + 1]);
                    mma16816(acc[am][na], ah[am], bl[g][o], bl[g][o + 1]);
                    mma16816(acc[am][na], al[am], bh[g][o], bh[g][o + 1]);
                }
        }
        __syncthreads();
    }

    // Epilogue: out = acc * inv[row]
    const int r0 = lane >> 2, c0 = (lane & 3) * 2;
#pragma unroll
    for (int am = 0; am < 2; am++) {
#pragma unroll
        for (int h = 0; h < 2; h++) {
            int lq = m0 + am * 16 + r0 + h * 8;
            float inv = s_inv[lq];
#pragma unroll
            for (int na = 0; na < 4; na++) {
                int gd = n0 + na * 8 + c0;
                size_t idx = ((size_t)b * SEQ + qb + lq) * DIM + gd;
                float2 o;
                o.x = acc[am][na][h * 2 + 0] * inv;
                o.y = acc[am][na][h * 2 + 1] * inv;
                *reinterpret_cast<float2*>(out + idx) = o;
            }
        }
    }
}

// ---------------------------------------------------------------------------
extern "C" void kernel_launch(void* const* d_in, const int* in_sizes, int n_in,
                              void* d_out, int out_size) {
    const float* inp  = (const float*)d_in[0];
    const float* w_k  = (const float*)d_in[1];
    const float* w_v  = (const float*)d_in[2];
    const int*   mask = (const int*)d_in[3];
    float* outp = (float*)d_out;

    const size_t BSD = (size_t)BATCH * SEQ * DIM;
    const size_t BSS = (size_t)BATCH * SEQ * SEQ;

    float* attn;
    if ((size_t)out_size >= BSD + BSS) {
        attn = outp + BSD;
    } else {
        void* p = nullptr;
        cudaGetSymbolAddress(&p, g_attn_fb);
        attn = (float*)p;
    }

    const int score_smem = 384 * SA * 2;                    // 104448
    const int pv_smem    = 2 * STAGE_ELEMS * 2;             // 106496
    cudaFuncSetAttribute(score_mma_kernel, cudaFuncAttributeMaxDynamicSharedMemorySize, score_smem);
    cudaFuncSetAttribute(normpv_kernel, cudaFuncAttributeMaxDynamicSharedMemorySize, pv_smem);

    prep_inp_kernel<<<(BATCH * SEQ * DIM) / (256 * 4), 256>>>(inp);
    proj_kernel<<<(BATCH * SEQ) / 128, 256>>>(inp, w_k, 0);
    proj_kernel<<<(BATCH * SEQ) / 128, 256>>>(inp, w_v, 1);
    score_mma_kernel<<<dim3(SEQ / 64, SEQ / 128, BATCH), 256, score_smem>>>(mask);
    sums_kernel<<<(BATCH * SEQ) / 256, 256>>>();
    normpv_kernel<<<dim3(SEQ / 64, BATCH), 256, pv_smem>>>(attn, outp);
}

// round 17
// speedup vs baseline: 1.0026x; 1.0007x over previous
#include <cuda_runtime.h>
#include <cuda_bf16.h>
#include <math.h>
#include <stdint.h>

#define BATCH 4
#define SEQ   4096
#define DIM   128

// Scratch (allocation-free: __device__ globals)
__device__ __nv_bfloat16 g_inp_hi[(size_t)BATCH * SEQ * DIM];
__device__ __nv_bfloat16 g_inp_lo[(size_t)BATCH * SEQ * DIM];
__device__ __nv_bfloat16 g_key_hi[(size_t)BATCH * SEQ * DIM];
__device__ __nv_bfloat16 g_key_lo[(size_t)BATCH * SEQ * DIM];
__device__ __nv_bfloat16 g_val_hi[(size_t)BATCH * SEQ * DIM];
__device__ __nv_bfloat16 g_val_lo[(size_t)BATCH * SEQ * DIM];
__device__ __nv_bfloat16 g_ehi[(size_t)BATCH * SEQ * SEQ];   // E split hi
__device__ __nv_bfloat16 g_elo[(size_t)BATCH * SEQ * SEQ];   // E split lo
__device__ float g_part[(size_t)BATCH * SEQ * 64];
__device__ float g_sinv[(size_t)BATCH * SEQ];
__device__ float g_attn_fb[(size_t)BATCH * SEQ * SEQ];

// ---------------------------------------------------------------------------
// Helpers
// ---------------------------------------------------------------------------
__device__ __forceinline__ uint32_t smem_u32(const void* p) {
    return (uint32_t)__cvta_generic_to_shared(p);
}
__device__ __forceinline__ void cp16(uint32_t dst, const void* src) {
    asm volatile("cp.async.cg.shared.global [%0], [%1], 16;\n" :: "r"(dst), "l"(src));
}
__device__ __forceinline__ void cp_commit() {
    asm volatile("cp.async.commit_group;\n" ::);
}
__device__ __forceinline__ void cp_wait0() {
    asm volatile("cp.async.wait_group 0;\n" ::);
}
__device__ __forceinline__ void cp_wait1() {
    asm volatile("cp.async.wait_group 1;\n" ::);
}
__device__ __forceinline__ void ldsm4(uint32_t& r0, uint32_t& r1, uint32_t& r2, uint32_t& r3,
                                      uint32_t addr) {
    asm volatile("ldmatrix.sync.aligned.m8n8.x4.shared.b16 {%0,%1,%2,%3},[%4];\n"
                 : "=r"(r0), "=r"(r1), "=r"(r2), "=r"(r3) : "r"(addr));
}
__device__ __forceinline__ void ldsm4t(uint32_t& r0, uint32_t& r1, uint32_t& r2, uint32_t& r3,
                                       uint32_t addr) {
    asm volatile("ldmatrix.sync.aligned.m8n8.x4.trans.shared.b16 {%0,%1,%2,%3},[%4];\n"
                 : "=r"(r0), "=r"(r1), "=r"(r2), "=r"(r3) : "r"(addr));
}
__device__ __forceinline__ void mma16816(float* c, const uint32_t* a, uint32_t b0, uint32_t b1) {
    asm volatile(
        "mma.sync.aligned.m16n8k16.row.col.f32.bf16.bf16.f32 "
        "{%0,%1,%2,%3},{%4,%5,%6,%7},{%8,%9},{%0,%1,%2,%3};\n"
        : "+f"(c[0]), "+f"(c[1]), "+f"(c[2]), "+f"(c[3])
        : "r"(a[0]), "r"(a[1]), "r"(a[2]), "r"(a[3]), "r"(b0), "r"(b1));
}
__device__ __forceinline__ uint32_t bf2pack(float x, float y) {
    __nv_bfloat162 h = __floats2bfloat162_rn(x, y);
    return *reinterpret_cast<uint32_t*>(&h);
}
__device__ __forceinline__ void split_store(float4 f, __nv_bfloat16* hp, __nv_bfloat16* lp) {
    float h0 = __bfloat162float(__float2bfloat16(f.x));
    float h1 = __bfloat162float(__float2bfloat16(f.y));
    float h2 = __bfloat162float(__float2bfloat16(f.z));
    float h3 = __bfloat162float(__float2bfloat16(f.w));
    uint2 hi, lo;
    hi.x = bf2pack(f.x, f.y);
    hi.y = bf2pack(f.z, f.w);
    lo.x = bf2pack(f.x - h0, f.y - h1);
    lo.y = bf2pack(f.z - h2, f.w - h3);
    *reinterpret_cast<uint2*>(hp) = hi;
    *reinterpret_cast<uint2*>(lp) = lo;
}

// ---------------------------------------------------------------------------
// Prep: split inp fp32 -> hi/lo bf16
// ---------------------------------------------------------------------------
__global__ void __launch_bounds__(256) prep_inp_kernel(const float* __restrict__ inp) {
    size_t s = (size_t)blockIdx.x * 256 + threadIdx.x;
    float4 f = *reinterpret_cast<const float4*>(inp + s * 4);
    split_store(f, g_inp_hi + s * 4, g_inp_lo + s * 4);
}

// ---------------------------------------------------------------------------
// Projection: out[m,e] = sum_d inp[m,d] * w[e,d]; writes split bf16 K or V.
// ---------------------------------------------------------------------------
__global__ void __launch_bounds__(256) proj_kernel(const float* __restrict__ inp,
                                                   const float* __restrict__ w,
                                                   int which) {
    __nv_bfloat16* ohi = which ? g_val_hi : g_key_hi;
    __nv_bfloat16* olo = which ? g_val_lo : g_key_lo;
    __shared__ float As[16][128];
    __shared__ float Bs[16][128];

    const int tid   = threadIdx.x;
    const int mbase = blockIdx.x * 128;
    const int tm    = tid >> 4;
    const int tn    = tid & 15;

    float acc[8][8];
#pragma unroll
    for (int i = 0; i < 8; i++)
#pragma unroll
        for (int j = 0; j < 8; j++) acc[i][j] = 0.f;

    const int lr  = tid >> 2;
    const int lc4 = tid & 3;

    for (int k0 = 0; k0 < DIM; k0 += 16) {
#pragma unroll
        for (int it = 0; it < 2; ++it) {
            int row = lr + it * 64;
            float4 a = *reinterpret_cast<const float4*>(inp + (size_t)(mbase + row) * DIM + k0 + lc4 * 4);
            As[lc4 * 4 + 0][row] = a.x; As[lc4 * 4 + 1][row] = a.y;
            As[lc4 * 4 + 2][row] = a.z; As[lc4 * 4 + 3][row] = a.w;
            float4 bv = *reinterpret_cast<const float4*>(w + (size_t)row * DIM + k0 + lc4 * 4);
            Bs[lc4 * 4 + 0][row] = bv.x; Bs[lc4 * 4 + 1][row] = bv.y;
            Bs[lc4 * 4 + 2][row] = bv.z; Bs[lc4 * 4 + 3][row] = bv.w;
        }
        __syncthreads();
#pragma unroll
        for (int k = 0; k < 16; k++) {
            float am[8], bn[8];
#pragma unroll
            for (int i = 0; i < 8; i++) am[i] = As[k][tm * 8 + i];
#pragma unroll
            for (int j = 0; j < 8; j++) bn[j] = Bs[k][tn * 8 + j];
#pragma unroll
            for (int i = 0; i < 8; i++)
#pragma unroll
                for (int j = 0; j < 8; j++) acc[i][j] = fmaf(am[i], bn[j], acc[i][j]);
        }
        __syncthreads();
    }
#pragma unroll
    for (int i = 0; i < 8; i++) {
        size_t o = (size_t)(mbase + tm * 8 + i) * DIM + tn * 8;
        split_store(make_float4(acc[i][0], acc[i][1], acc[i][2], acc[i][3]), ohi + o, olo + o);
        split_store(make_float4(acc[i][4], acc[i][5], acc[i][6], acc[i][7]), ohi + o + 4, olo + o + 4);
    }
}

// ---------------------------------------------------------------------------
// Score+exp: E = mask ? 0 : exp(score); writes E as split bf16 (hi/lo) + row sums.
// CTA = 128(q) x 64(k). 8 warps, warp tile 32x32. cp.async staging, mask prefetch.
// ---------------------------------------------------------------------------
#define SA 136

__global__ void __launch_bounds__(256, 2) score_mma_kernel(const int* __restrict__ mask) {
    extern __shared__ char smraw[];
    __nv_bfloat16* Ahi = (__nv_bfloat16*)smraw;     // [128][SA]
    __nv_bfloat16* Alo = Ahi + 128 * SA;
    __nv_bfloat16* Bhi = Alo + 128 * SA;            // [64][SA]
    __nv_bfloat16* Blo = Bhi + 64 * SA;
    __shared__ float ssum[2][128];

    const int b  = blockIdx.z;
    const int qt = blockIdx.y;
    const int kt = blockIdx.x;
    const int tid = threadIdx.x;

    const __nv_bfloat16* sa_hi = g_inp_hi + ((size_t)b * SEQ + qt * 128) * DIM;
    const __nv_bfloat16* sa_lo = g_inp_lo + ((size_t)b * SEQ + qt * 128) * DIM;
    const __nv_bfloat16* sb_hi = g_key_hi + ((size_t)b * SEQ + kt * 64) * DIM;
    const __nv_bfloat16* sb_lo = g_key_lo + ((size_t)b * SEQ + kt * 64) * DIM;

    // Stage A/B hi/lo via cp.async
#pragma unroll
    for (int i = 0; i < 8; i++) {
        int s = tid + i * 256;
        int row = s >> 4, c8 = (s & 15) * 8;
        cp16(smem_u32(Ahi + row * SA + c8), sa_hi + (size_t)row * DIM + c8);
        cp16(smem_u32(Alo + row * SA + c8), sa_lo + (size_t)row * DIM + c8);
    }
#pragma unroll
    for (int i = 0; i < 4; i++) {
        int s = tid + i * 256;
        int row = s >> 4, c8 = (s & 15) * 8;
        cp16(smem_u32(Bhi + row * SA + c8), sb_hi + (size_t)row * DIM + c8);
        cp16(smem_u32(Blo + row * SA + c8), sb_lo + (size_t)row * DIM + c8);
    }
    cp_commit();

    const int lane = tid & 31, warp = tid >> 5;
    const int m0 = (warp >> 1) * 32;
    const int n0 = (warp & 1) * 32;
    const int r0 = lane >> 2, c0 = (lane & 3) * 2;

    // Prefetch mask into a 16-bit register bitmask (hidden behind MMA phase).
    uint32_t mbits = 0;
#pragma unroll
    for (int am = 0; am < 2; am++)
#pragma unroll
        for (int h = 0; h < 2; h++)
#pragma unroll
            for (int na = 0; na < 4; na++) {
                int gq = qt * 128 + m0 + am * 16 + r0 + h * 8;
                int gk = kt * 64 + n0 + na * 8 + c0;
                size_t idx = ((size_t)b * SEQ + gq) * SEQ + gk;
                int2 mv = *reinterpret_cast<const int2*>(mask + idx);
                int c = (am * 2 + h) * 4 + na;
                mbits |= (mv.x ? 1u : 0u) << (2 * c);
                mbits |= (mv.y ? 1u : 0u) << (2 * c + 1);
            }

    cp_wait0();
    __syncthreads();

    float acc[2][4][4];
#pragma unroll
    for (int i = 0; i < 2; i++)
#pragma unroll
        for (int j = 0; j < 4; j++)
#pragma unroll
            for (int r = 0; r < 4; r++) acc[i][j][r] = 0.f;

    const int a_row = lane & 15;
    const int a_col = (lane >> 4) << 3;
    const int b_row = (lane & 7) + ((lane >> 4) << 3);
    const int b_col = ((lane >> 3) & 1) << 3;

#pragma unroll
    for (int ks = 0; ks < 8; ks++) {
        const int k = ks * 16;
        uint32_t ah[2][4], al[2][4];
#pragma unroll
        for (int am = 0; am < 2; am++) {
            uint32_t ad = smem_u32(Ahi + (m0 + am * 16 + a_row) * SA + k + a_col);
            ldsm4(ah[am][0], ah[am][1], ah[am][2], ah[am][3], ad);
            ad = smem_u32(Alo + (m0 + am * 16 + a_row) * SA + k + a_col);
            ldsm4(al[am][0], al[am][1], al[am][2], al[am][3], ad);
        }
        uint32_t bh[2][4], bl[2][4];
#pragma unroll
        for (int bn = 0; bn < 2; bn++) {
            uint32_t ad = smem_u32(Bhi + (n0 + bn * 16 + b_row) * SA + k + b_col);
            ldsm4(bh[bn][0], bh[bn][1], bh[bn][2], bh[bn][3], ad);
            ad = smem_u32(Blo + (n0 + bn * 16 + b_row) * SA + k + b_col);
            ldsm4(bl[bn][0], bl[bn][1], bl[bn][2], bl[bn][3], ad);
        }
#pragma unroll
        for (int am = 0; am < 2; am++)
#pragma unroll
            for (int na = 0; na < 4; na++) {
                const int g = na >> 1, o = (na & 1) * 2;
                mma16816(acc[am][na], ah[am], bh[g][o], bh[g][o + 1]);
                mma16816(acc[am][na], ah[am], bl[g][o], bl[g][o + 1]);
                mma16816(acc[am][na], al[am], bh[g][o], bh[g][o + 1]);
            }
    }

    // Epilogue: E = mask ? 0 : __expf(score*scale); write split bf16; row sums.
    const float scale = 0.08838834764831845f;
#pragma unroll
    for (int am = 0; am < 2; am++)
#pragma unroll
        for (int h = 0; h < 2; h++) {
            float rs = 0.f;
#pragma unroll
            for (int na = 0; na < 4; na++) {
                int gq = qt * 128 + m0 + am * 16 + r0 + h * 8;
                int gk = kt * 64 + n0 + na * 8 + c0;
                size_t idx = ((size_t)b * SEQ + gq) * SEQ + gk;
                int c = (am * 2 + h) * 4 + na;
                float ox = ((mbits >> (2 * c)) & 1u) ? 0.f : __expf(acc[am][na][h * 2 + 0] * scale);
                float oy = ((mbits >> (2 * c + 1)) & 1u) ? 0.f : __expf(acc[am][na][h * 2 + 1] * scale);
                rs += ox + oy;
                float hx = __bfloat162float(__float2bfloat16(ox));
                float hy = __bfloat162float(__float2bfloat16(oy));
                *reinterpret_cast<uint32_t*>(g_ehi + idx) = bf2pack(ox, oy);
                *reinterpret_cast<uint32_t*>(g_elo + idx) = bf2pack(ox - hx, oy - hy);
            }
            rs += __shfl_xor_sync(0xffffffffu, rs, 1);
            rs += __shfl_xor_sync(0xffffffffu, rs, 2);
            if ((lane & 3) == 0)
                ssum[warp & 1][m0 + am * 16 + r0 + h * 8] = rs;
        }
    __syncthreads();
    if (tid < 128) {
        g_part[((size_t)b * SEQ + qt * 128 + tid) * 64 + kt] = ssum[0][tid] + ssum[1][tid];
    }
}

// ---------------------------------------------------------------------------
// Row-sum reduce: s_inv[row] = 1 / sum_j part[row][j]
// ---------------------------------------------------------------------------
__global__ void __launch_bounds__(256) sums_kernel() {
    int row = blockIdx.x * 256 + threadIdx.x;
    const float* pp = g_part + (size_t)row * 64;
    float s = 0.f;
#pragma unroll
    for (int j = 0; j < 64; j += 4) {
        float4 v = *reinterpret_cast<const float4*>(pp + j);
        s += v.x + v.y + v.z + v.w;
    }
    g_sinv[row] = 1.f / s;
}

// ---------------------------------------------------------------------------
// Fused normalize + PV (normalization commutes with matmul):
//   out = diag(inv) * (E @ V);  attn = E * inv  (written from smem tile).
// CTA = 64(q) x 128(d); k-chunks of 64, cp.async double-buffered.
// 8 warps, warp tile 32x32. smem 2 stages x 53KB -> 2 CTAs/SM.
// ---------------------------------------------------------------------------
#define SE 72
#define SV 136
#define STAGE_ELEMS (2 * 64 * SE + 2 * 64 * SV)   // 26624 bf16 elems

__global__ void __launch_bounds__(256, 2) normpv_kernel(float* __restrict__ attn,
                                                        float* __restrict__ out) {
    extern __shared__ char smraw[];
    __nv_bfloat16* base = (__nv_bfloat16*)smraw;
    __shared__ float s_inv[64];

    const int b  = blockIdx.y;
    const int qb = blockIdx.x * 64;
    const int tid = threadIdx.x;

    const size_t ebase = ((size_t)b * SEQ + qb) * SEQ;
    const size_t vbase = (size_t)b * SEQ * DIM;

    if (tid < 64) s_inv[tid] = g_sinv[(size_t)b * SEQ + qb + tid];

    const int lane = tid & 31, warp = tid >> 5;
    const int m0 = (warp >> 2) * 32;   // q (2 groups)
    const int n0 = (warp & 3) * 32;    // d (4 groups)

    float acc[2][4][4];
#pragma unroll
    for (int i = 0; i < 2; i++)
#pragma unroll
        for (int j = 0; j < 4; j++)
#pragma unroll
            for (int r = 0; r < 4; r++) acc[i][j][r] = 0.f;

    const int a_row = lane & 15;
    const int a_col = (lane >> 4) << 3;
    const int v_row = (lane & 7) + (((lane >> 3) & 1) << 3);
    const int v_col = (lane >> 4) << 3;

    // Per-thread staging coordinates
    const int e_row = tid >> 3, e_c8 = (tid & 7) * 8;       // + i*32 rows? no: 2 iters cover 512 slots
    const int v_row_st = tid >> 4, v_c8 = (tid & 15) * 8;

    // issue one stage of cp.async loads
    auto issue_stage = [&](int kc, int buf) {
        __nv_bfloat16* Eh = base + (size_t)buf * STAGE_ELEMS;
        __nv_bfloat16* El = Eh + 64 * SE;
        __nv_bfloat16* Vh = El + 64 * SE;
        __nv_bfloat16* Vl = Vh + 64 * SV;
        const int kb = kc * 64;
#pragma unroll
        for (int i = 0; i < 2; i++) {
            int s = tid + i * 256;
            int row = s >> 3, c8 = (s & 7) * 8;
            cp16(smem_u32(Eh + row * SE + c8), g_ehi + ebase + (size_t)row * SEQ + kb + c8);
            cp16(smem_u32(El + row * SE + c8), g_elo + ebase + (size_t)row * SEQ + kb + c8);
        }
#pragma unroll
        for (int i = 0; i < 4; i++) {
            int s = tid + i * 256;
            int row = s >> 4, c8 = (s & 15) * 8;
            cp16(smem_u32(Vh + row * SV + c8), g_val_hi + vbase + (size_t)(kb + row) * DIM + c8);
            cp16(smem_u32(Vl + row * SV + c8), g_val_lo + vbase + (size_t)(kb + row) * DIM + c8);
        }
        cp_commit();
    };

    issue_stage(0, 0);

    for (int kc = 0; kc < SEQ / 64; kc++) {
        const int buf = kc & 1;
        if (kc + 1 < SEQ / 64) {
            issue_stage(kc + 1, (kc + 1) & 1);
            cp_wait1();
        } else {
            cp_wait0();
        }
        __syncthreads();

        __nv_bfloat16* Eh = base + (size_t)buf * STAGE_ELEMS;
        __nv_bfloat16* El = Eh + 64 * SE;
        __nv_bfloat16* Vh = El + 64 * SE;
        __nv_bfloat16* Vl = Vh + 64 * SV;
        const int kb = kc * 64;

        // attn = (hi+lo) * inv, written straight from the smem tile
#pragma unroll
        for (int i = 0; i < 2; i++) {
            int s = tid + i * 256;
            int row = s >> 3, c8 = (s & 7) * 8;
            uint4 h4 = *reinterpret_cast<const uint4*>(Eh + row * SE + c8);
            uint4 l4 = *reinterpret_cast<const uint4*>(El + row * SE + c8);
            float inv = s_inv[row];
            float4 o0, o1;
            {
                float2 h0 = __bfloat1622float2(*reinterpret_cast<__nv_bfloat162*>(&h4.x));
                float2 l0 = __bfloat1622float2(*reinterpret_cast<__nv_bfloat162*>(&l4.x));
                float2 h1 = __bfloat1622float2(*reinterpret_cast<__nv_bfloat162*>(&h4.y));
                float2 l1 = __bfloat1622float2(*reinterpret_cast<__nv_bfloat162*>(&l4.y));
                o0 = make_float4((h0.x + l0.x) * inv, (h0.y + l0.y) * inv,
                                 (h1.x + l1.x) * inv, (h1.y + l1.y) * inv);
                float2 h2 = __bfloat1622float2(*reinterpret_cast<__nv_bfloat162*>(&h4.z));
                float2 l2 = __bfloat1622float2(*reinterpret_cast<__nv_bfloat162*>(&l4.z));
                float2 h3 = __bfloat1622float2(*reinterpret_cast<__nv_bfloat162*>(&h4.w));
                float2 l3 = __bfloat1622float2(*reinterpret_cast<__nv_bfloat162*>(&l4.w));
                o1 = make_float4((h2.x + l2.x) * inv, (h2.y + l2.y) * inv,
                                 (h3.x + l3.x) * inv, (h3.y + l3.y) * inv);
            }
            float* ap = attn + ebase + (size_t)row * SEQ + kb + c8;
            *reinterpret_cast<float4*>(ap)     = o0;
            *reinterpret_cast<float4*>(ap + 4) = o1;
        }

        // MMA: acc += E_tile @ V_tile (split 3-pass)
#pragma unroll
        for (int ks = 0; ks < 4; ks++) {
            const int k = ks * 16;
            uint32_t ah[2][4], al[2][4];
#pragma unroll
            for (int am = 0; am < 2; am++) {
                uint32_t ad = smem_u32(Eh + (m0 + am * 16 + a_row) * SE + k + a_col);
                ldsm4(ah[am][0], ah[am][1], ah[am][2], ah[am][3], ad);
                ad = smem_u32(El + (m0 + am * 16 + a_row) * SE + k + a_col);
                ldsm4(al[am][0], al[am][1], al[am][2], al[am][3], ad);
            }
            uint32_t bh[2][4], bl[2][4];
#pragma unroll
            for (int bn = 0; bn < 2; bn++) {
                uint32_t ad = smem_u32(Vh + (k + v_row) * SV + n0 + bn * 16 + v_col);
                ldsm4t(bh[bn][0], bh[bn][1], bh[bn][2], bh[bn][3], ad);
                ad = smem_u32(Vl + (k + v_row) * SV + n0 + bn * 16 + v_col);
                ldsm4t(bl[bn][0], bl[bn][1], bl[bn][2], bl[bn][3], ad);
            }
#pragma unroll
            for (int am = 0; am < 2; am++)
#pragma unroll
                for (int na = 0; na < 4; na++) {
                    const int g = na >> 1, o = (na & 1) * 2;
                    mma16816(acc[am][na], ah[am], bh[g][o], bh[g][o + 1]);
                    mma16816(acc[am][na], ah[am], bl[g][o], bl[g][o + 1]);
                    mma16816(acc[am][na], al[am], bh[g][o], bh[g][o + 1]);
                }
        }
        __syncthreads();
    }

    // Epilogue: out = acc * inv[row]
    const int r0 = lane >> 2, c0 = (lane & 3) * 2;
#pragma unroll
    for (int am = 0; am < 2; am++) {
#pragma unroll
        for (int h = 0; h < 2; h++) {
            int lq = m0 + am * 16 + r0 + h * 8;
            float inv = s_inv[lq];
#pragma unroll
            for (int na = 0; na < 4; na++) {
                int gd = n0 + na * 8 + c0;
                size_t idx = ((size_t)b * SEQ + qb + lq) * DIM + gd;
                float2 o;
                o.x = acc[am][na][h * 2 + 0] * inv;
                o.y = acc[am][na][h * 2 + 1] * inv;
                *reinterpret_cast<float2*>(out + idx) = o;
            }
        }
    }
}

// ---------------------------------------------------------------------------
extern "C" void kernel_launch(void* const* d_in, const int* in_sizes, int n_in,
                              void* d_out, int out_size) {
    const float* inp  = (const float*)d_in[0];
    const float* w_k  = (const float*)d_in[1];
    const float* w_v  = (const float*)d_in[2];
    const int*   mask = (const int*)d_in[3];
    float* outp = (float*)d_out;

    const size_t BSD = (size_t)BATCH * SEQ * DIM;
    const size_t BSS = (size_t)BATCH * SEQ * SEQ;

    float* attn;
    if ((size_t)out_size >= BSD + BSS) {
        attn = outp + BSD;
    } else {
        void* p = nullptr;
        cudaGetSymbolAddress(&p, g_attn_fb);
        attn = (float*)p;
    }

    const int score_smem = 384 * SA * 2;                    // 104448
    const int pv_smem    = 2 * STAGE_ELEMS * 2;             // 106496
    cudaFuncSetAttribute(score_mma_kernel, cudaFuncAttributeMaxDynamicSharedMemorySize, score_smem);
    cudaFuncSetAttribute(normpv_kernel, cudaFuncAttributeMaxDynamicSharedMemorySize, pv_smem);

    prep_inp_kernel<<<(BATCH * SEQ * DIM) / (256 * 4), 256>>>(inp);
    proj_kernel<<<(BATCH * SEQ) / 128, 256>>>(inp, w_k, 0);
    proj_kernel<<<(BATCH * SEQ) / 128, 256>>>(inp, w_v, 1);
    score_mma_kernel<<<dim3(SEQ / 64, SEQ / 128, BATCH), 256, score_smem>>>(mask);
    sums_kernel<<<(BATCH * SEQ) / 256, 256>>>();
    normpv_kernel<<<dim3(SEQ / 64, BATCH), 256, pv_smem>>>(attn, outp);
}